// round 13
// baseline (speedup 1.0000x reference)
#include <cuda_runtime.h>
#include <cstdint>

#define BB 32
#define NN 4096
#define DD 768
#define KK 1024
#define CHUNK 512
#define NCHUNK 8
#define ROWS_PER_BLK 8

typedef unsigned long long u64;

__device__ int g_topk[BB * KK];
__device__ u64 g_scratch[BB * NN];   // per-batch: 8 sorted descending chunks

// Map float to uint with ascending unsigned order == ascending float order.
__device__ __forceinline__ unsigned f2ord(float f) {
    unsigned u = __float_as_uint(f);
    return (u & 0x80000000u) ? ~u : (u | 0x80000000u);
}

// ---------------------------------------------------------------------------
// Kernel A: low-serial-depth chunk sort.
// CTA (b,c), 512 threads, 1 key/thread, key = (ord << 12) | (4095 - idx)
// => jax.lax.top_k order (value desc, index asc); keys strictly distinct.
//  1) warp-local bitonic sort (32 keys, 15 shfl stages, registers only)
//  2) publish 16 descending runs to smem
//  3) rank = lane + sum over 15 other runs of count(> key); 5-step binary
//     search per run, 15-way ILP. COUNT FIX: the search returns 0..31 but the
//     true count is 0..32; for a descending run, count==32 iff run_min > key,
//     so add (run_min > key) after the search. Without this, ranks collide and
//     some sorted[] slots are never written -> stale smem -> nondeterminism
//     across graph replays (the round-12 failure).
//  4) ranks are a permutation of 0..511: scatter to smem, coalesced store.
// ---------------------------------------------------------------------------
__global__ __launch_bounds__(512) void sort_chunk_kernel(const float* __restrict__ sig) {
    __shared__ u64 runs[CHUNK];
    __shared__ u64 sorted[CHUNK];
    const int b    = blockIdx.x >> 3;
    const int c    = blockIdx.x & 7;
    const int t    = threadIdx.x;
    const int lane = t & 31;
    const int w    = t >> 5;            // warp id 0..15

    const int g = c * CHUNK + t;
    float v = sig[(size_t)b * NN + g];
    u64 r = ((u64)f2ord(v) << 12) | (u64)(4095 - g);

    // 1) warp bitonic sort, descending by lane (15 stages)
    #pragma unroll
    for (int k = 2; k <= 32; k <<= 1) {
        #pragma unroll
        for (int j = k >> 1; j > 0; j >>= 1) {
            bool keep_max = (((lane & k) == 0) == ((lane & j) == 0));
            u64 o = __shfl_xor_sync(0xffffffffu, r, j);
            r = keep_max ? (r > o ? r : o) : (r < o ? r : o);
        }
    }

    // 2) publish runs
    runs[w * 32 + lane] = r;
    __syncthreads();

    // 3) rank against the other 15 runs (independent search chains)
    int cnt[15];
    #pragma unroll
    for (int o = 0; o < 15; o++) cnt[o] = 0;

    #pragma unroll
    for (int s = 16; s >= 1; s >>= 1) {
        #pragma unroll
        for (int o = 0; o < 15; o++) {
            int ow = o + (o >= w ? 1 : 0);
            if (runs[ow * 32 + cnt[o] + s - 1] > r) cnt[o] += s;
        }
    }

    int rank = lane;
    #pragma unroll
    for (int o = 0; o < 15; o++) {
        int ow = o + (o >= w ? 1 : 0);
        // saturation fix: run fully greater than r => true count is 32
        rank += cnt[o] + (runs[ow * 32 + 31] > r ? 1 : 0);
    }

    // 4) scatter by rank, then coalesced global store
    sorted[rank] = r;
    __syncthreads();
    g_scratch[(size_t)b * NN + c * CHUNK + t] = sorted[t];
}

// ---------------------------------------------------------------------------
// Kernel B (+ PDL): rank-based merge across the 8 sorted chunks.
// rank = t + sum over the other 7 chunks of count(key' > key) via 7
// interleaved 9-step binary searches in smem. Same saturation fix applied
// (count can be 512 when an entire chunk exceeds the key).
// Write idx iff rank < 1024.
// ---------------------------------------------------------------------------
__global__ __launch_bounds__(512) void rank_merge_kernel() {
    __shared__ u64 sm[(NCHUNK - 1) * CHUNK];   // 7 x 512 keys = 28 KB
    const int b = blockIdx.x >> 3;
    const int c = blockIdx.x & 7;
    const int t = threadIdx.x;

    cudaGridDependencySynchronize();           // sort kernel fully complete

    const u64* base = g_scratch + (size_t)b * NN;

    #pragma unroll
    for (int o = 0; o < NCHUNK - 1; o++) {
        int oc = o + (o >= c ? 1 : 0);
        sm[o * CHUNK + t] = base[oc * CHUNK + t];
    }

    u64 key = base[c * CHUNK + t];
    __syncthreads();

    int cnt[NCHUNK - 1];
    #pragma unroll
    for (int o = 0; o < NCHUNK - 1; o++) cnt[o] = 0;

    #pragma unroll
    for (int s = CHUNK / 2; s >= 1; s >>= 1) {
        #pragma unroll
        for (int o = 0; o < NCHUNK - 1; o++) {
            if (sm[o * CHUNK + cnt[o] + s - 1] > key) cnt[o] += s;
        }
    }

    int rank = t;
    #pragma unroll
    for (int o = 0; o < NCHUNK - 1; o++) {
        // saturation fix: whole chunk greater => true count is CHUNK
        rank += cnt[o] + (sm[o * CHUNK + CHUNK - 1] > key ? 1 : 0);
    }

    if (rank < KK)
        g_topk[b * KK + rank] = 4095 - (int)(key & 0xFFFu);
}

// ---------------------------------------------------------------------------
// Gather (unchanged + PDL; ~28us wall = ~7.2TB/s effective, ~90% of spec):
// 8 rows/CTA, 192 threads, one float4 column each, MLP=8.
// ---------------------------------------------------------------------------
__global__ __launch_bounds__(192) void gather_kernel(const float4* __restrict__ x,
                                                     float4* __restrict__ out) {
    const int base = blockIdx.x * ROWS_PER_BLK;
    const int tid  = threadIdx.x;

    cudaGridDependencySynchronize();           // merge kernel fully complete

    const float4* srcs[ROWS_PER_BLK];
    #pragma unroll
    for (int r = 0; r < ROWS_PER_BLK; r++) {
        int row = base + r;
        int b   = row / (KK + 1);
        int rr  = row - b * (KK + 1);
        int src_row = (rr == 0) ? 0 : (1 + g_topk[b * KK + rr - 1]);
        srcs[r] = x + ((size_t)b * (NN + 1) + (size_t)src_row) * (DD / 4);
    }

    float4 vals[ROWS_PER_BLK];
    #pragma unroll
    for (int r = 0; r < ROWS_PER_BLK; r++)
        vals[r] = __ldcs(srcs[r] + tid);

    #pragma unroll
    for (int r = 0; r < ROWS_PER_BLK; r++)
        out[(size_t)(base + r) * (DD / 4) + tid] = vals[r];
}

extern "C" void kernel_launch(void* const* d_in, const int* in_sizes, int n_in,
                              void* d_out, int out_size) {
    const float* x   = (const float*)d_in[0];   // [B, N+1, D] fp32
    const float* sig = (const float*)d_in[1];   // [B, N] fp32
    (void)in_sizes; (void)n_in; (void)out_size;

    sort_chunk_kernel<<<BB * NCHUNK, CHUNK>>>(sig);

    cudaLaunchAttribute attr[1];
    attr[0].id = cudaLaunchAttributeProgrammaticStreamSerialization;
    attr[0].val.programmaticStreamSerializationAllowed = 1;

    {
        cudaLaunchConfig_t cfg = {};
        cfg.gridDim  = dim3(BB * NCHUNK);
        cfg.blockDim = dim3(CHUNK);
        cfg.stream   = 0;
        cfg.attrs    = attr;
        cfg.numAttrs = 1;
        cudaLaunchKernelEx(&cfg, rank_merge_kernel);
    }
    {
        cudaLaunchConfig_t cfg = {};
        cfg.gridDim  = dim3(BB * (KK + 1) / ROWS_PER_BLK);
        cfg.blockDim = dim3(192);
        cfg.stream   = 0;
        cfg.attrs    = attr;
        cfg.numAttrs = 1;
        cudaLaunchKernelEx(&cfg, gather_kernel, (const float4*)x, (float4*)d_out);
    }
}

// round 14
// speedup vs baseline: 1.0358x; 1.0358x over previous
#include <cuda_runtime.h>
#include <cstdint>

#define BB 32
#define NN 4096
#define DD 768
#define KK 1024
#define CHUNK 512
#define NCHUNK 8
#define ROWS_PER_BLK 8

typedef unsigned long long u64;

__device__ int g_topk[BB * KK];
__device__ u64 g_scratch[BB * NN];   // flat: chunk cg occupies [cg*512, cg*512+512)

// Map float to uint with ascending unsigned order == ascending float order.
__device__ __forceinline__ unsigned f2ord(float f) {
    unsigned u = __float_as_uint(f);
    return (u & 0x80000000u) ? ~u : (u | 0x80000000u);
}

// ---------------------------------------------------------------------------
// Kernel A: bitonic chunk sort, TWO independent chunks per CTA for ILP.
// Thread t holds key t of chunk 2*cta and key t of chunk 2*cta+1. The 45-stage
// network (R8/R11, measured-good) runs on both keys simultaneously: predicates
// depend only on t (computed once), shfl stages issue two independent
// SHFL->CMP->SEL streams, smem stages share one barrier pair for both chunks.
// Composite key (ord << 12) | (4095 - idx) => jax.lax.top_k order
// (value desc, index asc); keys strictly distinct.
// sig is [BB][NN] and NN = 8*CHUNK, so chunk cg is contiguous at cg*512.
// ---------------------------------------------------------------------------
__global__ __launch_bounds__(512) void sort_chunk_kernel(const float* __restrict__ sig) {
    __shared__ u64 sm[2 * CHUNK];
    const int cta = blockIdx.x;          // 0..127
    const int t   = threadIdx.x;
    const int cgA = 2 * cta;             // global chunk ids
    const int cgB = 2 * cta + 1;

    float vA = sig[cgA * CHUNK + t];
    float vB = sig[cgB * CHUNK + t];
    int idxA = (cgA & 7) * CHUNK + t;    // index within batch
    int idxB = (cgB & 7) * CHUNK + t;
    u64 rA = ((u64)f2ord(vA) << 12) | (u64)(4095 - idxA);
    u64 rB = ((u64)f2ord(vB) << 12) | (u64)(4095 - idxB);

    #pragma unroll
    for (int k = 2; k <= CHUNK; k <<= 1) {
        #pragma unroll
        for (int j = k >> 1; j > 0; j >>= 1) {
            bool keep_max = (((t & k) == 0) == ((t & j) == 0));
            u64 oA, oB;
            if (j >= 32) {
                __syncthreads();
                sm[t] = rA;
                sm[CHUNK + t] = rB;
                __syncthreads();
                oA = sm[t ^ j];
                oB = sm[CHUNK + (t ^ j)];
            } else {
                oA = __shfl_xor_sync(0xffffffffu, rA, j);
                oB = __shfl_xor_sync(0xffffffffu, rB, j);
            }
            rA = keep_max ? (rA > oA ? rA : oA) : (rA < oA ? rA : oA);
            rB = keep_max ? (rB > oB ? rB : oB) : (rB < oB ? rB : oB);
        }
    }

    g_scratch[(size_t)cgA * CHUNK + t] = rA;
    g_scratch[(size_t)cgB * CHUNK + t] = rB;
}

// ---------------------------------------------------------------------------
// Kernel B (+ PDL): rank-based merge across the 8 sorted chunks of a batch.
// rank = t + sum over the other 7 chunks of count(key' > key) via 7
// interleaved 9-step binary searches in smem, PLUS the saturation fix:
// the search returns 0..511 but the true count is 0..512 (whole chunk
// greater => add (chunk_min > key)). Without it ranks collide and holes in
// g_topk keep stale values across graph replays (round-12 failure mode).
// Write idx iff rank < 1024.
// ---------------------------------------------------------------------------
__global__ __launch_bounds__(512) void rank_merge_kernel() {
    __shared__ u64 sm[(NCHUNK - 1) * CHUNK];   // 7 x 512 keys = 28 KB
    const int b = blockIdx.x >> 3;
    const int c = blockIdx.x & 7;
    const int t = threadIdx.x;

    cudaGridDependencySynchronize();           // sort kernel fully complete

    const u64* base = g_scratch + (size_t)b * NN;

    #pragma unroll
    for (int o = 0; o < NCHUNK - 1; o++) {
        int oc = o + (o >= c ? 1 : 0);
        sm[o * CHUNK + t] = base[oc * CHUNK + t];
    }

    u64 key = base[c * CHUNK + t];
    __syncthreads();

    int cnt[NCHUNK - 1];
    #pragma unroll
    for (int o = 0; o < NCHUNK - 1; o++) cnt[o] = 0;

    #pragma unroll
    for (int s = CHUNK / 2; s >= 1; s >>= 1) {
        #pragma unroll
        for (int o = 0; o < NCHUNK - 1; o++) {
            if (sm[o * CHUNK + cnt[o] + s - 1] > key) cnt[o] += s;
        }
    }

    int rank = t;
    #pragma unroll
    for (int o = 0; o < NCHUNK - 1; o++) {
        // saturation fix: whole chunk greater => true count is CHUNK
        rank += cnt[o] + (sm[o * CHUNK + CHUNK - 1] > key ? 1 : 0);
    }

    if (rank < KK)
        g_topk[b * KK + rank] = 4095 - (int)(key & 0xFFFu);
}

// ---------------------------------------------------------------------------
// Gather (unchanged + PDL; ~28us wall = ~7.2TB/s effective, ~90% of spec):
// 8 rows/CTA, 192 threads, one float4 column each, MLP=8.
// ---------------------------------------------------------------------------
__global__ __launch_bounds__(192) void gather_kernel(const float4* __restrict__ x,
                                                     float4* __restrict__ out) {
    const int base = blockIdx.x * ROWS_PER_BLK;
    const int tid  = threadIdx.x;

    cudaGridDependencySynchronize();           // merge kernel fully complete

    const float4* srcs[ROWS_PER_BLK];
    #pragma unroll
    for (int r = 0; r < ROWS_PER_BLK; r++) {
        int row = base + r;
        int b   = row / (KK + 1);
        int rr  = row - b * (KK + 1);
        int src_row = (rr == 0) ? 0 : (1 + g_topk[b * KK + rr - 1]);
        srcs[r] = x + ((size_t)b * (NN + 1) + (size_t)src_row) * (DD / 4);
    }

    float4 vals[ROWS_PER_BLK];
    #pragma unroll
    for (int r = 0; r < ROWS_PER_BLK; r++)
        vals[r] = __ldcs(srcs[r] + tid);

    #pragma unroll
    for (int r = 0; r < ROWS_PER_BLK; r++)
        out[(size_t)(base + r) * (DD / 4) + tid] = vals[r];
}

extern "C" void kernel_launch(void* const* d_in, const int* in_sizes, int n_in,
                              void* d_out, int out_size) {
    const float* x   = (const float*)d_in[0];   // [B, N+1, D] fp32
    const float* sig = (const float*)d_in[1];   // [B, N] fp32
    (void)in_sizes; (void)n_in; (void)out_size;

    sort_chunk_kernel<<<BB * NCHUNK / 2, CHUNK>>>(sig);

    cudaLaunchAttribute attr[1];
    attr[0].id = cudaLaunchAttributeProgrammaticStreamSerialization;
    attr[0].val.programmaticStreamSerializationAllowed = 1;

    {
        cudaLaunchConfig_t cfg = {};
        cfg.gridDim  = dim3(BB * NCHUNK);
        cfg.blockDim = dim3(CHUNK);
        cfg.stream   = 0;
        cfg.attrs    = attr;
        cfg.numAttrs = 1;
        cudaLaunchKernelEx(&cfg, rank_merge_kernel);
    }
    {
        cudaLaunchConfig_t cfg = {};
        cfg.gridDim  = dim3(BB * (KK + 1) / ROWS_PER_BLK);
        cfg.blockDim = dim3(192);
        cfg.stream   = 0;
        cfg.attrs    = attr;
        cfg.numAttrs = 1;
        cudaLaunchKernelEx(&cfg, gather_kernel, (const float4*)x, (float4*)d_out);
    }
}